// round 1
// baseline (speedup 1.0000x reference)
#include <cuda_runtime.h>
#include <math.h>

// Problem constants
#define BSZ    8
#define LSEQ   1024
#define DMODEL 1024
#define NSTATE 16
#define MTOT   (BSZ * LSEQ)        // 8192 rows
#define XTOT   (MTOT * DMODEL)     // 8388608 elements

// ---------------------------------------------------------------------------
// Scratch (static __device__ arrays — no allocation allowed)
// ---------------------------------------------------------------------------
__device__ __align__(256) float g_xnorm[XTOT];
__device__ __align__(256) float g_xin[XTOT];
__device__ __align__(256) float g_z[XTOT];
__device__ __align__(256) float g_dt[XTOT];
__device__ __align__(256) float g_Bt[MTOT * NSTATE];
__device__ __align__(256) float g_Ct[MTOT * NSTATE];
__device__ __align__(256) float g_ssm[XTOT];

// ---------------------------------------------------------------------------
// LayerNorm: one block per row (d=1024), 256 threads, float4 vectorized
// ---------------------------------------------------------------------------
__global__ __launch_bounds__(256) void layernorm_kernel(
    const float* __restrict__ x,
    const float* __restrict__ g,
    const float* __restrict__ b)
{
    int row = blockIdx.x;
    int t = threadIdx.x;
    const float4* xr = reinterpret_cast<const float4*>(x + (size_t)row * DMODEL);
    float4 v = xr[t];

    float s  = v.x + v.y + v.z + v.w;
    float sq = v.x * v.x + v.y * v.y + v.z * v.z + v.w * v.w;
    #pragma unroll
    for (int o = 16; o; o >>= 1) {
        s  += __shfl_xor_sync(0xffffffffu, s,  o);
        sq += __shfl_xor_sync(0xffffffffu, sq, o);
    }
    __shared__ float ssum[8], ssq[8];
    __shared__ float sh_mean, sh_rstd;
    int w = t >> 5;
    if ((t & 31) == 0) { ssum[w] = s; ssq[w] = sq; }
    __syncthreads();
    if (t == 0) {
        float S = 0.f, Q = 0.f;
        #pragma unroll
        for (int i = 0; i < 8; i++) { S += ssum[i]; Q += ssq[i]; }
        float mu  = S * (1.0f / DMODEL);
        float var = Q * (1.0f / DMODEL) - mu * mu;
        sh_mean = mu;
        sh_rstd = rsqrtf(var + 1e-5f);
    }
    __syncthreads();
    float mean = sh_mean, rstd = sh_rstd;

    float4 gg = reinterpret_cast<const float4*>(g)[t];
    float4 bb = reinterpret_cast<const float4*>(b)[t];
    float4 o;
    o.x = (v.x - mean) * rstd * gg.x + bb.x;
    o.y = (v.y - mean) * rstd * gg.y + bb.y;
    o.z = (v.z - mean) * rstd * gg.z + bb.z;
    o.w = (v.w - mean) * rstd * gg.w + bb.w;
    reinterpret_cast<float4*>(g_xnorm + (size_t)row * DMODEL)[t] = o;
}

// ---------------------------------------------------------------------------
// Tiled SGEMM:  C[m, n] = sum_k A[m, k] * B[n, k]    (both K-major)
// EPI: 0 = plain store to C[m*N+n]
//      1 = split at DMODEL:  n<DMODEL -> C (x_in), else C2 (z)   (both [M, DMODEL])
//      2 = softplus(acc + aux[n]) -> C[m*N+n]        (dt)
//      3 = acc + aux[m*N+n]       -> C[m*N+n]        (residual output)
// ---------------------------------------------------------------------------
template<int BM, int BN, int BK, int TM, int TN, int EPI>
__global__ __launch_bounds__((BM / TM) * (BN / TN)) void sgemm_kernel(
    const float* __restrict__ A,
    const float* __restrict__ Bm,
    float* __restrict__ C,
    float* __restrict__ C2,
    const float* __restrict__ aux,
    int M, int N, int K)
{
    constexpr int TX = BN / TN;
    constexpr int TY = BM / TM;
    constexpr int NT = TX * TY;
    constexpr int PAD = 4;

    __shared__ float As[BK][BM + PAD];
    __shared__ float Bs[BK][BN + PAD];

    int tid = threadIdx.x;
    int bn = blockIdx.x * BN;
    int bm = blockIdx.y * BM;
    int tx = tid % TX;
    int ty = tid / TX;

    float acc[TM][TN];
    #pragma unroll
    for (int i = 0; i < TM; i++)
        #pragma unroll
        for (int j = 0; j < TN; j++) acc[i][j] = 0.f;

    const float* Ag = A  + (size_t)bm * K;
    const float* Bg = Bm + (size_t)bn * K;

    for (int k0 = 0; k0 < K; k0 += BK) {
        // Load A tile (BM x BK), store transposed As[k][m]
        #pragma unroll 2
        for (int i = tid; i < BM * (BK / 4); i += NT) {
            int r  = i / (BK / 4);
            int c4 = i % (BK / 4);
            float4 v = *reinterpret_cast<const float4*>(Ag + (size_t)r * K + k0 + c4 * 4);
            As[c4 * 4 + 0][r] = v.x;
            As[c4 * 4 + 1][r] = v.y;
            As[c4 * 4 + 2][r] = v.z;
            As[c4 * 4 + 3][r] = v.w;
        }
        // Load B tile (BN x BK), store transposed Bs[k][n]
        #pragma unroll 2
        for (int i = tid; i < BN * (BK / 4); i += NT) {
            int r  = i / (BK / 4);
            int c4 = i % (BK / 4);
            float4 v = *reinterpret_cast<const float4*>(Bg + (size_t)r * K + k0 + c4 * 4);
            Bs[c4 * 4 + 0][r] = v.x;
            Bs[c4 * 4 + 1][r] = v.y;
            Bs[c4 * 4 + 2][r] = v.z;
            Bs[c4 * 4 + 3][r] = v.w;
        }
        __syncthreads();

        #pragma unroll
        for (int kk = 0; kk < BK; kk++) {
            float a[TM], bv[TN];
            #pragma unroll
            for (int i = 0; i < TM; i++) a[i] = As[kk][ty * TM + i];
            #pragma unroll
            for (int j = 0; j < TN; j++) bv[j] = Bs[kk][tx * TN + j];
            #pragma unroll
            for (int i = 0; i < TM; i++)
                #pragma unroll
                for (int j = 0; j < TN; j++)
                    acc[i][j] += a[i] * bv[j];
        }
        __syncthreads();
    }

    // Epilogue
    #pragma unroll
    for (int i = 0; i < TM; i++) {
        int m = bm + ty * TM + i;
        #pragma unroll
        for (int j = 0; j < TN; j++) {
            int n = bn + tx * TN + j;
            float v = acc[i][j];
            if constexpr (EPI == 1) {
                if (n < DMODEL) C[(size_t)m * DMODEL + n] = v;
                else            C2[(size_t)m * DMODEL + (n - DMODEL)] = v;
            } else if constexpr (EPI == 2) {
                v += aux[n];
                v = (v > 20.f) ? v : log1pf(expf(v));
                C[(size_t)m * N + n] = v;
            } else if constexpr (EPI == 3) {
                C[(size_t)m * N + n] = v + aux[(size_t)m * N + n];
            } else {
                C[(size_t)m * N + n] = v;
            }
        }
    }
}

// ---------------------------------------------------------------------------
// Sequential SSM scan, fused with silu(z)/D epilogue.
// Thread = (b, d, n). 512 blocks x 256 threads = 131072 threads.
// Warp = 2 d-values x 16 n-lanes; reduce over n with 4 shfl_xor inside the
// 16-lane group.
// ---------------------------------------------------------------------------
__global__ __launch_bounds__(256) void scan_kernel(
    const float* __restrict__ A_log,
    const float* __restrict__ h_prev,
    const float* __restrict__ Dvec,
    float* __restrict__ h_out)
{
    int b  = blockIdx.x >> 6;          // 8 batches
    int dg = blockIdx.x & 63;          // 64 d-groups of 16
    int n  = threadIdx.x & 15;
    int dl = threadIdx.x >> 4;         // 0..15
    int d  = dg * 16 + dl;

    float Acoef = -__expf(A_log[d * NSTATE + n]);
    float h  = h_prev[((size_t)b * DMODEL + d) * NSTATE + n];
    float Dd = Dvec[d];

    size_t base_bd = (size_t)b * LSEQ * DMODEL + d;
    size_t base_bn = (size_t)b * LSEQ * NSTATE + n;

    for (int t = 0; t < LSEQ; t++) {
        size_t idx  = base_bd + (size_t)t * DMODEL;
        size_t idxn = base_bn + (size_t)t * NSTATE;
        float dtv = g_dt[idx];
        float xin = g_xin[idx];
        float Btv = g_Bt[idxn];
        float Ctv = g_Ct[idxn];

        float dA = __expf(dtv * Acoef);
        h = dA * h + (dtv * xin) * Btv;
        float y = h * Ctv;
        y += __shfl_xor_sync(0xffffffffu, y, 1);
        y += __shfl_xor_sync(0xffffffffu, y, 2);
        y += __shfl_xor_sync(0xffffffffu, y, 4);
        y += __shfl_xor_sync(0xffffffffu, y, 8);

        if (n == 0) {
            float zv  = g_z[idx];
            float sil = zv / (1.f + __expf(-zv));
            g_ssm[idx] = y * sil + xin * Dd;
        }
    }
    h_out[((size_t)b * DMODEL + d) * NSTATE + n] = h;
}

// ---------------------------------------------------------------------------
// Launch
// ---------------------------------------------------------------------------
extern "C" void kernel_launch(void* const* d_in, const int* in_sizes, int n_in,
                              void* d_out, int out_size)
{
    const float* x      = (const float*)d_in[0];
    const float* h_prev = (const float*)d_in[1];
    const float* ln_g   = (const float*)d_in[2];
    const float* ln_b   = (const float*)d_in[3];
    const float* W_ig   = (const float*)d_in[4];
    const float* W_dt   = (const float*)d_in[5];
    const float* b_dt   = (const float*)d_in[6];
    const float* A_log  = (const float*)d_in[7];
    const float* W_B    = (const float*)d_in[8];
    const float* W_C    = (const float*)d_in[9];
    const float* Dv     = (const float*)d_in[10];
    const float* W_out  = (const float*)d_in[11];
    float* out = (float*)d_out;

    float *p_xnorm, *p_xin, *p_z, *p_dt, *p_Bt, *p_Ct, *p_ssm;
    cudaGetSymbolAddress((void**)&p_xnorm, g_xnorm);
    cudaGetSymbolAddress((void**)&p_xin,   g_xin);
    cudaGetSymbolAddress((void**)&p_z,     g_z);
    cudaGetSymbolAddress((void**)&p_dt,    g_dt);
    cudaGetSymbolAddress((void**)&p_Bt,    g_Bt);
    cudaGetSymbolAddress((void**)&p_Ct,    g_Ct);
    cudaGetSymbolAddress((void**)&p_ssm,   g_ssm);

    // 1. LayerNorm
    layernorm_kernel<<<MTOT, 256>>>(x, ln_g, ln_b);

    // 2. x_proj = x_norm @ W_ig^T  (split into x_in | z)
    {
        dim3 grid(2048 / 128, MTOT / 128);
        sgemm_kernel<128, 128, 16, 8, 8, 1><<<grid, 256>>>(
            p_xnorm, W_ig, p_xin, p_z, nullptr, MTOT, 2048, DMODEL);
    }

    // 3. dt = softplus(x_in @ W_dt^T + b_dt)
    {
        dim3 grid(DMODEL / 128, MTOT / 128);
        sgemm_kernel<128, 128, 16, 8, 8, 2><<<grid, 256>>>(
            p_xin, W_dt, p_dt, nullptr, b_dt, MTOT, DMODEL, DMODEL);
    }

    // 4. B_t = x_in @ W_B^T ; C_t = x_in @ W_C^T   (N = 16 each)
    {
        dim3 grid(1, MTOT / 128);
        sgemm_kernel<128, 16, 16, 4, 2, 0><<<grid, 256>>>(
            p_xin, W_B, p_Bt, nullptr, nullptr, MTOT, NSTATE, DMODEL);
        sgemm_kernel<128, 16, 16, 4, 2, 0><<<grid, 256>>>(
            p_xin, W_C, p_Ct, nullptr, nullptr, MTOT, NSTATE, DMODEL);
    }

    // 5. Sequential scan + fused silu/D epilogue -> g_ssm, h_final -> out tail
    scan_kernel<<<BSZ * 64, 256>>>(A_log, h_prev, Dv, out + XTOT);

    // 6. out = x + ssm_out @ W_out^T
    {
        dim3 grid(DMODEL / 128, MTOT / 128);
        sgemm_kernel<128, 128, 16, 8, 8, 3><<<grid, 256>>>(
            p_ssm, W_out, out, nullptr, x, MTOT, DMODEL, DMODEL);
    }
}

// round 2
// speedup vs baseline: 1.5823x; 1.5823x over previous
#include <cuda_runtime.h>
#include <math.h>
#include <stdint.h>

// Problem constants
#define BSZ    8
#define LSEQ   1024
#define DMODEL 1024
#define NSTATE 16
#define MTOT   (BSZ * LSEQ)        // 8192 rows
#define XTOT   (MTOT * DMODEL)     // 8388608 elements

// ---------------------------------------------------------------------------
// Scratch (static __device__ arrays — no allocation allowed)
// ---------------------------------------------------------------------------
__device__ __align__(256) float g_xnorm[XTOT];
__device__ __align__(256) float g_xin[XTOT];
__device__ __align__(256) float g_z[XTOT];
__device__ __align__(256) float g_dt[XTOT];
__device__ __align__(256) float g_Bt[MTOT * NSTATE];
__device__ __align__(256) float g_Ct[MTOT * NSTATE];
__device__ __align__(256) float g_ssm[XTOT];

// ---------------------------------------------------------------------------
// Helpers
// ---------------------------------------------------------------------------
__device__ __forceinline__ uint32_t f2tf(float f) {
    uint32_t u;
    asm("cvt.rna.tf32.f32 %0, %1;" : "=r"(u) : "f"(f));
    return u;
}

__device__ __forceinline__ void mma_tf32(float* c, const uint32_t* a, const uint32_t* b) {
    asm volatile(
        "mma.sync.aligned.m16n8k8.row.col.f32.tf32.tf32.f32 "
        "{%0,%1,%2,%3}, {%4,%5,%6,%7}, {%8,%9}, {%0,%1,%2,%3};"
        : "+f"(c[0]), "+f"(c[1]), "+f"(c[2]), "+f"(c[3])
        : "r"(a[0]), "r"(a[1]), "r"(a[2]), "r"(a[3]), "r"(b[0]), "r"(b[1]));
}

__device__ __forceinline__ float softplus_f(float v) {
    return (v > 20.f) ? v : log1pf(expf(v));
}

// ---------------------------------------------------------------------------
// LayerNorm: one block per row (d=1024), 256 threads, float4 vectorized
// ---------------------------------------------------------------------------
__global__ __launch_bounds__(256) void layernorm_kernel(
    const float* __restrict__ x,
    const float* __restrict__ g,
    const float* __restrict__ b)
{
    int row = blockIdx.x;
    int t = threadIdx.x;
    const float4* xr = reinterpret_cast<const float4*>(x + (size_t)row * DMODEL);
    float4 v = xr[t];

    float s  = v.x + v.y + v.z + v.w;
    float sq = v.x * v.x + v.y * v.y + v.z * v.z + v.w * v.w;
    #pragma unroll
    for (int o = 16; o; o >>= 1) {
        s  += __shfl_xor_sync(0xffffffffu, s,  o);
        sq += __shfl_xor_sync(0xffffffffu, sq, o);
    }
    __shared__ float ssum[8], ssq[8];
    __shared__ float sh_mean, sh_rstd;
    int w = t >> 5;
    if ((t & 31) == 0) { ssum[w] = s; ssq[w] = sq; }
    __syncthreads();
    if (t == 0) {
        float S = 0.f, Q = 0.f;
        #pragma unroll
        for (int i = 0; i < 8; i++) { S += ssum[i]; Q += ssq[i]; }
        float mu  = S * (1.0f / DMODEL);
        float var = Q * (1.0f / DMODEL) - mu * mu;
        sh_mean = mu;
        sh_rstd = rsqrtf(var + 1e-5f);
    }
    __syncthreads();
    float mean = sh_mean, rstd = sh_rstd;

    float4 gg = reinterpret_cast<const float4*>(g)[t];
    float4 bb = reinterpret_cast<const float4*>(b)[t];
    float4 o;
    o.x = (v.x - mean) * rstd * gg.x + bb.x;
    o.y = (v.y - mean) * rstd * gg.y + bb.y;
    o.z = (v.z - mean) * rstd * gg.z + bb.z;
    o.w = (v.w - mean) * rstd * gg.w + bb.w;
    reinterpret_cast<float4*>(g_xnorm + (size_t)row * DMODEL)[t] = o;
}

// ---------------------------------------------------------------------------
// TF32 tensor-core GEMM:  C[m, n] = sum_k A[m, k] * B[n, k]   (both K-major)
// Tile 128x128, BK=32, 256 threads = 8 warps as 2(m) x 4(n); warp tile 64x32.
// SMEM layout: [kk4][m][4] with per-kk4 stride 520 words -> conflict-free
// fragment LDS (bank = 4g + t4 permutation) and 16B-aligned STS.128.
// EPI: 0 plain, 1 split x_in|z at DMODEL, 2 softplus(+bias), 3 +residual
// ---------------------------------------------------------------------------
#define SSTRIDE 520   // 128*4 + 8 words per kk4 slab

template<int EPI>
__global__ __launch_bounds__(256) void gemm_tf32(
    const float* __restrict__ A,
    const float* __restrict__ Bm,
    float* __restrict__ C,
    float* __restrict__ C2,
    const float* __restrict__ aux,
    int M, int N, int K)
{
    __shared__ uint32_t sA[8 * SSTRIDE];
    __shared__ uint32_t sB[8 * SSTRIDE];

    const int tid  = threadIdx.x;
    const int bm   = blockIdx.y * 128;
    const int bn   = blockIdx.x * 128;
    const int wid  = tid >> 5;
    const int lane = tid & 31;
    const int wm   = wid >> 2;      // 0..1
    const int wn   = wid & 3;       // 0..3
    const int g    = lane >> 2;     // 0..7
    const int t4   = lane & 3;      // 0..3

    const float* Agp = A  + (size_t)bm * K;
    const float* Bgp = Bm + (size_t)bn * K;

    float acc[4][4][4];
    #pragma unroll
    for (int i = 0; i < 4; i++)
        #pragma unroll
        for (int j = 0; j < 4; j++)
            #pragma unroll
            for (int r = 0; r < 4; r++) acc[i][j][r] = 0.f;

    float4 rA[4], rB[4];

    // prologue LDG of tile 0
    #pragma unroll
    for (int it = 0; it < 4; it++) {
        int i = tid + it * 256;
        int row = i >> 3, c4 = i & 7;
        rA[it] = *reinterpret_cast<const float4*>(Agp + (size_t)row * K + c4 * 4);
        rB[it] = *reinterpret_cast<const float4*>(Bgp + (size_t)row * K + c4 * 4);
    }

    const uint32_t* sAm = sA + (wm * 64) * 4 + t4;
    const uint32_t* sBn = sB + (wn * 32) * 4 + t4;

    for (int k0 = 0; k0 < K; k0 += 32) {
        // STS (with tf32 convert)
        #pragma unroll
        for (int it = 0; it < 4; it++) {
            int i = tid + it * 256;
            int row = i >> 3, c4 = i & 7;
            uint4 a4, b4;
            a4.x = f2tf(rA[it].x); a4.y = f2tf(rA[it].y);
            a4.z = f2tf(rA[it].z); a4.w = f2tf(rA[it].w);
            b4.x = f2tf(rB[it].x); b4.y = f2tf(rB[it].y);
            b4.z = f2tf(rB[it].z); b4.w = f2tf(rB[it].w);
            *reinterpret_cast<uint4*>(&sA[c4 * SSTRIDE + row * 4]) = a4;
            *reinterpret_cast<uint4*>(&sB[c4 * SSTRIDE + row * 4]) = b4;
        }
        __syncthreads();

        // prefetch next tile
        if (k0 + 32 < K) {
            #pragma unroll
            for (int it = 0; it < 4; it++) {
                int i = tid + it * 256;
                int row = i >> 3, c4 = i & 7;
                rA[it] = *reinterpret_cast<const float4*>(Agp + (size_t)row * K + k0 + 32 + c4 * 4);
                rB[it] = *reinterpret_cast<const float4*>(Bgp + (size_t)row * K + k0 + 32 + c4 * 4);
            }
        }

        // compute: 4 k8-steps
        #pragma unroll
        for (int s = 0; s < 4; s++) {
            const int lo = (2 * s) * SSTRIDE;
            const int hi = lo + SSTRIDE;
            uint32_t af[4][4], bf[4][2];
            #pragma unroll
            for (int mt = 0; mt < 4; mt++) {
                int mo = (mt * 16 + g) * 4;
                af[mt][0] = sAm[lo + mo];
                af[mt][1] = sAm[lo + mo + 32];   // (m+8)*4
                af[mt][2] = sAm[hi + mo];
                af[mt][3] = sAm[hi + mo + 32];
            }
            #pragma unroll
            for (int nt = 0; nt < 4; nt++) {
                int no = (nt * 8 + g) * 4;
                bf[nt][0] = sBn[lo + no];
                bf[nt][1] = sBn[hi + no];
            }
            #pragma unroll
            for (int mt = 0; mt < 4; mt++)
                #pragma unroll
                for (int nt = 0; nt < 4; nt++)
                    mma_tf32(acc[mt][nt], af[mt], bf[nt]);
        }
        __syncthreads();
    }

    // Epilogue
    #pragma unroll
    for (int mt = 0; mt < 4; mt++) {
        #pragma unroll
        for (int nt = 0; nt < 4; nt++) {
            int m0 = bm + wm * 64 + mt * 16 + g;
            int n0 = bn + wn * 32 + nt * 8 + 2 * t4;
            float* cc = acc[mt][nt];
            #pragma unroll
            for (int half = 0; half < 2; half++) {
                int m = m0 + half * 8;
                float v0 = cc[half * 2 + 0];
                float v1 = cc[half * 2 + 1];
                if constexpr (EPI == 1) {
                    if (n0 < DMODEL) {
                        *reinterpret_cast<float2*>(&C[(size_t)m * DMODEL + n0]) = make_float2(v0, v1);
                    } else {
                        *reinterpret_cast<float2*>(&C2[(size_t)m * DMODEL + n0 - DMODEL]) = make_float2(v0, v1);
                    }
                } else if constexpr (EPI == 2) {
                    v0 = softplus_f(v0 + aux[n0]);
                    v1 = softplus_f(v1 + aux[n0 + 1]);
                    *reinterpret_cast<float2*>(&C[(size_t)m * N + n0]) = make_float2(v0, v1);
                } else if constexpr (EPI == 3) {
                    float2 r = *reinterpret_cast<const float2*>(&aux[(size_t)m * N + n0]);
                    *reinterpret_cast<float2*>(&C[(size_t)m * N + n0]) = make_float2(v0 + r.x, v1 + r.y);
                } else {
                    *reinterpret_cast<float2*>(&C[(size_t)m * N + n0]) = make_float2(v0, v1);
                }
            }
        }
    }
}

// ---------------------------------------------------------------------------
// Fused B_t / C_t kernel: one pass over x_in, both 16-wide outputs.
// grid = 256 blocks (32 rows each), 256 threads.
// thread = (row = tid>>3, colgroup = tid&7 -> 4 cols of [B|C] 32-wide output)
// ---------------------------------------------------------------------------
__global__ __launch_bounds__(256) void bc_kernel(
    const float* __restrict__ X,
    const float* __restrict__ WB,
    const float* __restrict__ WC,
    float* __restrict__ Bt,
    float* __restrict__ Ct)
{
    __shared__ float sX[32][33];
    __shared__ float sW[32][33];

    int tid = threadIdx.x;
    int bm  = blockIdx.x * 32;
    int row = tid >> 3;
    int cg  = tid & 7;

    float acc[4] = {0.f, 0.f, 0.f, 0.f};

    for (int k0 = 0; k0 < DMODEL; k0 += 32) {
        #pragma unroll
        for (int it = 0; it < 4; it++) {
            int i = tid + it * 256;
            int r = i >> 5, kk = i & 31;
            sX[r][kk] = X[(size_t)(bm + r) * DMODEL + k0 + kk];
        }
        #pragma unroll
        for (int it = 0; it < 4; it++) {
            int i = tid + it * 256;
            int c = i >> 5, kk = i & 31;
            float w = (c < 16) ? WB[c * DMODEL + k0 + kk]
                               : WC[(c - 16) * DMODEL + k0 + kk];
            sW[kk][c] = w;
        }
        __syncthreads();
        #pragma unroll
        for (int kk = 0; kk < 32; kk++) {
            float a = sX[row][kk];
            const float* wr = &sW[kk][cg * 4];
            acc[0] += a * wr[0];
            acc[1] += a * wr[1];
            acc[2] += a * wr[2];
            acc[3] += a * wr[3];
        }
        __syncthreads();
    }

    int m = bm + row;
    float4 v = make_float4(acc[0], acc[1], acc[2], acc[3]);
    if (cg < 4) *reinterpret_cast<float4*>(&Bt[(size_t)m * NSTATE + cg * 4]) = v;
    else        *reinterpret_cast<float4*>(&Ct[(size_t)m * NSTATE + (cg - 4) * 4]) = v;
}

// ---------------------------------------------------------------------------
// Sequential SSM scan, fused with silu(z)/D epilogue.
// ---------------------------------------------------------------------------
__global__ __launch_bounds__(256) void scan_kernel(
    const float* __restrict__ A_log,
    const float* __restrict__ h_prev,
    const float* __restrict__ Dvec,
    float* __restrict__ h_out)
{
    int b  = blockIdx.x >> 6;
    int dg = blockIdx.x & 63;
    int n  = threadIdx.x & 15;
    int dl = threadIdx.x >> 4;
    int d  = dg * 16 + dl;

    float Acoef = -__expf(A_log[d * NSTATE + n]);
    float h  = h_prev[((size_t)b * DMODEL + d) * NSTATE + n];
    float Dd = Dvec[d];

    size_t base_bd = (size_t)b * LSEQ * DMODEL + d;
    size_t base_bn = (size_t)b * LSEQ * NSTATE + n;

    for (int t = 0; t < LSEQ; t++) {
        size_t idx  = base_bd + (size_t)t * DMODEL;
        size_t idxn = base_bn + (size_t)t * NSTATE;
        float dtv = g_dt[idx];
        float xin = g_xin[idx];
        float Btv = g_Bt[idxn];
        float Ctv = g_Ct[idxn];

        float dA = __expf(dtv * Acoef);
        h = dA * h + (dtv * xin) * Btv;
        float y = h * Ctv;
        y += __shfl_xor_sync(0xffffffffu, y, 1);
        y += __shfl_xor_sync(0xffffffffu, y, 2);
        y += __shfl_xor_sync(0xffffffffu, y, 4);
        y += __shfl_xor_sync(0xffffffffu, y, 8);

        if (n == 0) {
            float zv  = g_z[idx];
            float sil = zv / (1.f + __expf(-zv));
            g_ssm[idx] = y * sil + xin * Dd;
        }
    }
    h_out[((size_t)b * DMODEL + d) * NSTATE + n] = h;
}

// ---------------------------------------------------------------------------
// Launch
// ---------------------------------------------------------------------------
extern "C" void kernel_launch(void* const* d_in, const int* in_sizes, int n_in,
                              void* d_out, int out_size)
{
    const float* x      = (const float*)d_in[0];
    const float* h_prev = (const float*)d_in[1];
    const float* ln_g   = (const float*)d_in[2];
    const float* ln_b   = (const float*)d_in[3];
    const float* W_ig   = (const float*)d_in[4];
    const float* W_dt   = (const float*)d_in[5];
    const float* b_dt   = (const float*)d_in[6];
    const float* A_log  = (const float*)d_in[7];
    const float* W_B    = (const float*)d_in[8];
    const float* W_C    = (const float*)d_in[9];
    const float* Dv     = (const float*)d_in[10];
    const float* W_out  = (const float*)d_in[11];
    float* out = (float*)d_out;

    float *p_xnorm, *p_xin, *p_z, *p_dt, *p_Bt, *p_Ct, *p_ssm;
    cudaGetSymbolAddress((void**)&p_xnorm, g_xnorm);
    cudaGetSymbolAddress((void**)&p_xin,   g_xin);
    cudaGetSymbolAddress((void**)&p_z,     g_z);
    cudaGetSymbolAddress((void**)&p_dt,    g_dt);
    cudaGetSymbolAddress((void**)&p_Bt,    g_Bt);
    cudaGetSymbolAddress((void**)&p_Ct,    g_Ct);
    cudaGetSymbolAddress((void**)&p_ssm,   g_ssm);

    // 1. LayerNorm
    layernorm_kernel<<<MTOT, 256>>>(x, ln_g, ln_b);

    // 2. x_proj = x_norm @ W_ig^T  (split into x_in | z)  [tf32 tensor core]
    {
        dim3 grid(2048 / 128, MTOT / 128);
        gemm_tf32<1><<<grid, 256>>>(p_xnorm, W_ig, p_xin, p_z, nullptr, MTOT, 2048, DMODEL);
    }

    // 3. dt = softplus(x_in @ W_dt^T + b_dt)  [tf32 tensor core]
    {
        dim3 grid(DMODEL / 128, MTOT / 128);
        gemm_tf32<2><<<grid, 256>>>(p_xin, W_dt, p_dt, nullptr, b_dt, MTOT, DMODEL, DMODEL);
    }

    // 4. B_t and C_t fused (single pass over x_in)
    bc_kernel<<<MTOT / 32, 256>>>(p_xin, W_B, W_C, p_Bt, p_Ct);

    // 5. Sequential scan + fused silu/D epilogue -> g_ssm, h_final -> out tail
    scan_kernel<<<BSZ * 64, 256>>>(A_log, h_prev, Dv, out + XTOT);

    // 6. out = x + ssm_out @ W_out^T  [tf32 tensor core]
    {
        dim3 grid(DMODEL / 128, MTOT / 128);
        gemm_tf32<3><<<grid, 256>>>(p_ssm, W_out, out, nullptr, x, MTOT, DMODEL, DMODEL);
    }
}

// round 4
// speedup vs baseline: 1.9560x; 1.2362x over previous
#include <cuda_runtime.h>
#include <math.h>
#include <stdint.h>

// Problem constants
#define BSZ    8
#define LSEQ   1024
#define DMODEL 1024
#define NSTATE 16
#define MTOT   (BSZ * LSEQ)        // 8192
#define XTOT   (MTOT * DMODEL)     // 8388608
#define KDIM   1024

// GEMM tiling
#define BM 128
#define BN 128
#define BK 32
#define NSTG 3
#define NCHUNK (KDIM / BK)          // 32
#define SSTRIDE 520                 // words per kk4 slab (128*4 + 8 pad)
#define ASTAGE_W (8 * SSTRIDE)      // 4160 words per operand per stage
#define STAGE_W  (2 * ASTAGE_W)     // 8320 words
#define SMEM_DYN (NSTG * STAGE_W * 4)   // 99840 bytes

// N sizes
#define N1 2048
#define N2 1280                     // 1024 dt + 16 B + 16 C + 224 pad
#define N3 1024

// ---------------------------------------------------------------------------
// Scratch
// ---------------------------------------------------------------------------
__device__ __align__(256) float g_xnorm[XTOT];          // tf32-rounded
__device__ __align__(256) float g_xin[XTOT];            // fp32 (scan)
__device__ __align__(256) float g_xin_r[XTOT];          // tf32-rounded (gemm A)
__device__ __align__(256) float g_z[XTOT];
__device__ __align__(256) float g_dt[XTOT];
__device__ __align__(256) float g_Bt[MTOT * NSTATE];
__device__ __align__(256) float g_Ct[MTOT * NSTATE];
__device__ __align__(256) float g_ssm[XTOT];            // tf32-rounded
__device__ __align__(256) float g_wigr[N1 * KDIM];      // rounded W_ig
__device__ __align__(256) float g_wbc[N2 * KDIM];       // rounded [W_dt;W_B;W_C;0]
__device__ __align__(256) float g_woutr[N3 * KDIM];     // rounded W_out

// ---------------------------------------------------------------------------
// Helpers
// ---------------------------------------------------------------------------
__device__ __forceinline__ uint32_t f2tf(float f) {
    uint32_t u;
    asm("cvt.rna.tf32.f32 %0, %1;" : "=r"(u) : "f"(f));
    return u;
}
__device__ __forceinline__ float f2tf_f(float f) { return __uint_as_float(f2tf(f)); }

__device__ __forceinline__ void mma_tf32(float* c, const uint32_t* a, const uint32_t* b) {
    asm volatile(
        "mma.sync.aligned.m16n8k8.row.col.f32.tf32.tf32.f32 "
        "{%0,%1,%2,%3}, {%4,%5,%6,%7}, {%8,%9}, {%0,%1,%2,%3};"
        : "+f"(c[0]), "+f"(c[1]), "+f"(c[2]), "+f"(c[3])
        : "r"(a[0]), "r"(a[1]), "r"(a[2]), "r"(a[3]), "r"(b[0]), "r"(b[1]));
}

__device__ __forceinline__ uint32_t smem_u32(const void* p) {
    uint32_t a;
    asm("{ .reg .u64 t; cvta.to.shared.u64 t, %1; cvt.u32.u64 %0, t; }" : "=r"(a) : "l"(p));
    return a;
}
__device__ __forceinline__ void cp16(uint32_t dst, const float* src) {
    asm volatile("cp.async.cg.shared.global [%0], [%1], 16;"
                 :: "r"(dst), "l"(__cvta_generic_to_global(src)));
}
#define CP_COMMIT() asm volatile("cp.async.commit_group;")
#define CP_WAIT1()  asm volatile("cp.async.wait_group 1;" ::: "memory")

__device__ __forceinline__ float softplus_f(float v) {
    return (v > 20.f) ? v : log1pf(expf(v));
}

// ---------------------------------------------------------------------------
// LayerNorm (tf32-rounded output; sole consumer is gemm1's A operand)
// ---------------------------------------------------------------------------
__global__ __launch_bounds__(256) void layernorm_kernel(
    const float* __restrict__ x,
    const float* __restrict__ g,
    const float* __restrict__ b)
{
    int row = blockIdx.x;
    int t = threadIdx.x;
    float4 v = reinterpret_cast<const float4*>(x + (size_t)row * DMODEL)[t];

    float s  = v.x + v.y + v.z + v.w;
    float sq = v.x * v.x + v.y * v.y + v.z * v.z + v.w * v.w;
    #pragma unroll
    for (int o = 16; o; o >>= 1) {
        s  += __shfl_xor_sync(0xffffffffu, s,  o);
        sq += __shfl_xor_sync(0xffffffffu, sq, o);
    }
    __shared__ float ssum[8], ssq[8], sh_mean, sh_rstd;
    int w = t >> 5;
    if ((t & 31) == 0) { ssum[w] = s; ssq[w] = sq; }
    __syncthreads();
    if (t == 0) {
        float S = 0.f, Q = 0.f;
        #pragma unroll
        for (int i = 0; i < 8; i++) { S += ssum[i]; Q += ssq[i]; }
        float mu  = S * (1.0f / DMODEL);
        float var = Q * (1.0f / DMODEL) - mu * mu;
        sh_mean = mu;
        sh_rstd = rsqrtf(var + 1e-5f);
    }
    __syncthreads();
    float mean = sh_mean, rstd = sh_rstd;

    float4 gg = reinterpret_cast<const float4*>(g)[t];
    float4 bb = reinterpret_cast<const float4*>(b)[t];
    float4 o;
    o.x = f2tf_f((v.x - mean) * rstd * gg.x + bb.x);
    o.y = f2tf_f((v.y - mean) * rstd * gg.y + bb.y);
    o.z = f2tf_f((v.z - mean) * rstd * gg.z + bb.z);
    o.w = f2tf_f((v.w - mean) * rstd * gg.w + bb.w);
    reinterpret_cast<float4*>(g_xnorm + (size_t)row * DMODEL)[t] = o;
}

// ---------------------------------------------------------------------------
// Weight prep: tf32-round all B operands; assemble fused [W_dt; W_B; W_C; 0]
// ---------------------------------------------------------------------------
__global__ __launch_bounds__(256) void prep_kernel(
    const float* __restrict__ W_ig,
    const float* __restrict__ W_dt,
    const float* __restrict__ W_B,
    const float* __restrict__ W_C,
    const float* __restrict__ W_out)
{
    const int K4 = KDIM / 4;
    int stride = gridDim.x * blockDim.x;
    const int nig  = N1 * K4;
    const int nbc  = 1056 * K4;
    const int nout = N3 * K4;
    int total = nig + nbc + nout;
    for (int i = blockIdx.x * blockDim.x + threadIdx.x; i < total; i += stride) {
        const float4* src;
        float4* dst;
        if (i < nig) {
            src = reinterpret_cast<const float4*>(W_ig) + i;
            dst = reinterpret_cast<float4*>(g_wigr) + i;
        } else if (i < nig + nbc) {
            int j = i - nig;
            int row = j / K4;
            int c4  = j % K4;
            const float* s;
            if (row < 1024)      s = W_dt + (size_t)row * KDIM;
            else if (row < 1040) s = W_B + (size_t)(row - 1024) * KDIM;
            else                 s = W_C + (size_t)(row - 1040) * KDIM;
            src = reinterpret_cast<const float4*>(s) + c4;
            dst = reinterpret_cast<float4*>(g_wbc) + j;
        } else {
            int j = i - nig - nbc;
            src = reinterpret_cast<const float4*>(W_out) + j;
            dst = reinterpret_cast<float4*>(g_woutr) + j;
        }
        float4 v = *src;
        v.x = f2tf_f(v.x); v.y = f2tf_f(v.y); v.z = f2tf_f(v.z); v.w = f2tf_f(v.w);
        *dst = v;
    }
}

// ---------------------------------------------------------------------------
// TF32 mma.sync GEMM with cp.async 3-stage pipeline.
// C[m,n] = sum_k A[m,k]*B[n,k]; tile 128x128, 8 warps (2m x 4n), warp 64x32.
// SMEM layout per stage: [kk4][m][4] slabs, stride SSTRIDE words (R2-proven).
// EPI 1: n<1024 -> O0 (fp32 x_in) + O2 (tf32 copy); else O1 (z)
// EPI 2: n<1024 -> softplus(v+aux[n]) -> O0; 1024-1039 -> O1(Bt);
//        1040-1055 -> O2(Ct); else discard
// EPI 3: O0 = v + aux[m*1024+n]
// ---------------------------------------------------------------------------
template<int EPI>
__global__ __launch_bounds__(256) void gemm_ma(
    const float* __restrict__ A,
    const float* __restrict__ Bw,
    float* __restrict__ O0,
    float* __restrict__ O1,
    float* __restrict__ O2,
    const float* __restrict__ aux)
{
    extern __shared__ uint32_t dsm[];
    const uint32_t dsm_addr = smem_u32(dsm);

    const int tid  = threadIdx.x;
    const int wid  = tid >> 5;
    const int lane = tid & 31;
    const int bm   = blockIdx.y * BM;
    const int bn   = blockIdx.x * BN;
    const int wm   = wid >> 2;
    const int wn   = wid & 3;
    const int g    = lane >> 2;
    const int t4   = lane & 3;

    const float* Ag = A  + (size_t)bm * KDIM;
    const float* Bg = Bw + (size_t)bn * KDIM;

    const int lrow = tid >> 3;      // 0..31 (+k*32)
    const int lc4  = tid & 7;

    // issue cp.async for one chunk into one stage
    auto load_chunk = [&](int c, int stg) {
        uint32_t base = dsm_addr + (uint32_t)(stg * STAGE_W * 4);
        uint32_t wdst = (uint32_t)((lc4 * SSTRIDE) * 4);
        #pragma unroll
        for (int it = 0; it < 4; it++) {
            int row = lrow + it * 32;
            cp16(base + wdst + (uint32_t)(row * 16),
                 Ag + (size_t)row * KDIM + c * BK + lc4 * 4);
        }
        uint32_t baseB = base + (uint32_t)(ASTAGE_W * 4);
        #pragma unroll
        for (int it = 0; it < 4; it++) {
            int row = lrow + it * 32;
            cp16(baseB + wdst + (uint32_t)(row * 16),
                 Bg + (size_t)row * KDIM + c * BK + lc4 * 4);
        }
    };

    float acc[4][4][4];
    #pragma unroll
    for (int i = 0; i < 4; i++)
        #pragma unroll
        for (int j = 0; j < 4; j++)
            #pragma unroll
            for (int r = 0; r < 4; r++) acc[i][j][r] = 0.f;

    // prologue: chunks 0,1
    load_chunk(0, 0); CP_COMMIT();
    load_chunk(1, 1); CP_COMMIT();

    for (int c = 0; c < NCHUNK; c++) {
        CP_WAIT1();
        __syncthreads();

        // issue loads for c+2 (stage (c+2)%3 == (c-1)%3, safe post-barrier)
        if (c + 2 < NCHUNK) load_chunk(c + 2, (c + 2) % NSTG);
        CP_COMMIT();

        // compute chunk c from stage c%3
        const uint32_t* sA = dsm + (c % NSTG) * STAGE_W;
        const uint32_t* sB = sA + ASTAGE_W;
        const uint32_t* sAm = sA + (wm * 64) * 4 + t4;
        const uint32_t* sBn = sB + (wn * 32) * 4 + t4;

        #pragma unroll
        for (int s = 0; s < 4; s++) {
            const int lo = (2 * s) * SSTRIDE;
            const int hi = lo + SSTRIDE;
            uint32_t af[4][4], bf[4][2];
            #pragma unroll
            for (int mt = 0; mt < 4; mt++) {
                int mo = (mt * 16 + g) * 4;
                af[mt][0] = sAm[lo + mo];
                af[mt][1] = sAm[lo + mo + 32];
                af[mt][2] = sAm[hi + mo];
                af[mt][3] = sAm[hi + mo + 32];
            }
            #pragma unroll
            for (int nt = 0; nt < 4; nt++) {
                int no = (nt * 8 + g) * 4;
                bf[nt][0] = sBn[lo + no];
                bf[nt][1] = sBn[hi + no];
            }
            #pragma unroll
            for (int mt = 0; mt < 4; mt++)
                #pragma unroll
                for (int nt = 0; nt < 4; nt++)
                    mma_tf32(acc[mt][nt], af[mt], bf[nt]);
        }
        __syncthreads();
    }

    // Epilogue
    #pragma unroll
    for (int mt = 0; mt < 4; mt++) {
        #pragma unroll
        for (int nt = 0; nt < 4; nt++) {
            int m0 = bm + wm * 64 + mt * 16 + g;
            int n0 = bn + wn * 32 + nt * 8 + 2 * t4;
            float* cc = acc[mt][nt];
            #pragma unroll
            for (int half = 0; half < 2; half++) {
                int m = m0 + half * 8;
                float v0 = cc[half * 2 + 0];
                float v1 = cc[half * 2 + 1];
                if constexpr (EPI == 1) {
                    if (n0 < DMODEL) {
                        *reinterpret_cast<float2*>(&O0[(size_t)m * DMODEL + n0]) = make_float2(v0, v1);
                        *reinterpret_cast<float2*>(&O2[(size_t)m * DMODEL + n0]) =
                            make_float2(f2tf_f(v0), f2tf_f(v1));
                    } else {
                        *reinterpret_cast<float2*>(&O1[(size_t)m * DMODEL + n0 - DMODEL]) = make_float2(v0, v1);
                    }
                } else if constexpr (EPI == 2) {
                    if (n0 < DMODEL) {
                        v0 = softplus_f(v0 + aux[n0]);
                        v1 = softplus_f(v1 + aux[n0 + 1]);
                        *reinterpret_cast<float2*>(&O0[(size_t)m * DMODEL + n0]) = make_float2(v0, v1);
                    } else if (n0 < 1040) {
                        *reinterpret_cast<float2*>(&O1[(size_t)m * NSTATE + (n0 - 1024)]) = make_float2(v0, v1);
                    } else if (n0 < 1056) {
                        *reinterpret_cast<float2*>(&O2[(size_t)m * NSTATE + (n0 - 1040)]) = make_float2(v0, v1);
                    }
                } else { // EPI == 3
                    float2 r = *reinterpret_cast<const float2*>(&aux[(size_t)m * DMODEL + n0]);
                    *reinterpret_cast<float2*>(&O0[(size_t)m * DMODEL + n0]) = make_float2(v0 + r.x, v1 + r.y);
                }
            }
        }
    }
}

// ---------------------------------------------------------------------------
// Sequential SSM scan + fused silu/D epilogue, 1-step-ahead prefetch.
// Thread = (b, d, n); 16 n-lanes reduce via shfl. ssm written tf32-rounded.
// ---------------------------------------------------------------------------
__global__ __launch_bounds__(256) void scan_kernel(
    const float* __restrict__ A_log,
    const float* __restrict__ h_prev,
    const float* __restrict__ Dvec,
    float* __restrict__ h_out)
{
    int b  = blockIdx.x >> 6;
    int dg = blockIdx.x & 63;
    int n  = threadIdx.x & 15;
    int dl = threadIdx.x >> 4;
    int d  = dg * 16 + dl;

    float Acoef = -__expf(A_log[d * NSTATE + n]);
    float h  = h_prev[((size_t)b * DMODEL + d) * NSTATE + n];
    float Dd = Dvec[d];

    size_t idx  = (size_t)b * LSEQ * DMODEL + d;
    size_t idxn = (size_t)b * LSEQ * NSTATE + n;

    float dtv = g_dt[idx];
    float xin = g_xin[idx];
    float Btv = g_Bt[idxn];
    float Ctv = g_Ct[idxn];
    float zv  = g_z[idx];

    for (int t = 0; t < LSEQ; t++) {
        float n_dt = 0.f, n_xin = 0.f, n_Bt = 0.f, n_Ct = 0.f, n_z = 0.f;
        if (t + 1 < LSEQ) {
            n_dt  = g_dt[idx + DMODEL];
            n_xin = g_xin[idx + DMODEL];
            n_Bt  = g_Bt[idxn + NSTATE];
            n_Ct  = g_Ct[idxn + NSTATE];
            n_z   = g_z[idx + DMODEL];
        }

        float dA = __expf(dtv * Acoef);
        h = dA * h + (dtv * xin) * Btv;
        float y = h * Ctv;
        y += __shfl_xor_sync(0xffffffffu, y, 1);
        y += __shfl_xor_sync(0xffffffffu, y, 2);
        y += __shfl_xor_sync(0xffffffffu, y, 4);
        y += __shfl_xor_sync(0xffffffffu, y, 8);

        if (n == 0) {
            float sil = zv / (1.f + __expf(-zv));
            g_ssm[idx] = f2tf_f(y * sil + xin * Dd);
        }

        dtv = n_dt; xin = n_xin; Btv = n_Bt; Ctv = n_Ct; zv = n_z;
        idx += DMODEL; idxn += NSTATE;
    }
    h_out[((size_t)b * DMODEL + d) * NSTATE + n] = h;
}

// ---------------------------------------------------------------------------
// Launch
// ---------------------------------------------------------------------------
extern "C" void kernel_launch(void* const* d_in, const int* in_sizes, int n_in,
                              void* d_out, int out_size)
{
    const float* x      = (const float*)d_in[0];
    const float* h_prev = (const float*)d_in[1];
    const float* ln_g   = (const float*)d_in[2];
    const float* ln_b   = (const float*)d_in[3];
    const float* W_ig   = (const float*)d_in[4];
    const float* W_dt   = (const float*)d_in[5];
    const float* b_dt   = (const float*)d_in[6];
    const float* A_log  = (const float*)d_in[7];
    const float* W_B    = (const float*)d_in[8];
    const float* W_C    = (const float*)d_in[9];
    const float* Dv     = (const float*)d_in[10];
    const float* W_out  = (const float*)d_in[11];
    float* out = (float*)d_out;

    float *p_xnorm, *p_xin, *p_xin_r, *p_z, *p_dt, *p_Bt, *p_Ct, *p_ssm;
    float *p_wigr, *p_wbc, *p_woutr;
    cudaGetSymbolAddress((void**)&p_xnorm, g_xnorm);
    cudaGetSymbolAddress((void**)&p_xin,   g_xin);
    cudaGetSymbolAddress((void**)&p_xin_r, g_xin_r);
    cudaGetSymbolAddress((void**)&p_z,     g_z);
    cudaGetSymbolAddress((void**)&p_dt,    g_dt);
    cudaGetSymbolAddress((void**)&p_Bt,    g_Bt);
    cudaGetSymbolAddress((void**)&p_Ct,    g_Ct);
    cudaGetSymbolAddress((void**)&p_ssm,   g_ssm);
    cudaGetSymbolAddress((void**)&p_wigr,  g_wigr);
    cudaGetSymbolAddress((void**)&p_wbc,   g_wbc);
    cudaGetSymbolAddress((void**)&p_woutr, g_woutr);

    cudaFuncSetAttribute(gemm_ma<1>, cudaFuncAttributeMaxDynamicSharedMemorySize, SMEM_DYN);
    cudaFuncSetAttribute(gemm_ma<2>, cudaFuncAttributeMaxDynamicSharedMemorySize, SMEM_DYN);
    cudaFuncSetAttribute(gemm_ma<3>, cudaFuncAttributeMaxDynamicSharedMemorySize, SMEM_DYN);

    // 0. weight prep (tf32 rounding + fused W' assembly)
    prep_kernel<<<2048, 256>>>(W_ig, W_dt, W_B, W_C, W_out);

    // 1. LayerNorm (tf32-rounded output)
    layernorm_kernel<<<MTOT, 256>>>(x, ln_g, ln_b);

    // 2. x_proj = x_norm @ W_ig^T -> x_in (fp32 + tf32 copy) | z
    {
        dim3 grid(N1 / BN, MTOT / BM);
        gemm_ma<1><<<grid, 256, SMEM_DYN>>>(p_xnorm, p_wigr, p_xin, p_z, p_xin_r, nullptr);
    }

    // 3. fused: dt = softplus(x_in@W_dt^T + b_dt); Bt; Ct
    {
        dim3 grid(N2 / BN, MTOT / BM);
        gemm_ma<2><<<grid, 256, SMEM_DYN>>>(p_xin_r, p_wbc, p_dt, p_Bt, p_Ct, b_dt);
    }

    // 4. scan -> g_ssm (tf32-rounded), h_final -> out tail
    scan_kernel<<<BSZ * 64, 256>>>(A_log, h_prev, Dv, out + XTOT);

    // 5. out = x + ssm @ W_out^T
    {
        dim3 grid(N3 / BN, MTOT / BM);
        gemm_ma<3><<<grid, 256, SMEM_DYN>>>(p_ssm, p_woutr, out, nullptr, nullptr, x);
    }
}